// round 2
// baseline (speedup 1.0000x reference)
#include <cuda_runtime.h>
#include <cuda_bf16.h>
#include <math.h>

// Problem constants
#define BATCH 8
#define NDIM  1024   // N (query axis, softmax axis)
#define MEDIM 1024   // ME
#define DDIM  1024   // D

// Tiling
#define BM 128
#define BN 128
#define BK 16
#define TM 8
#define TN 8
// 256 threads = 16x16 thread grid, each 8x8 microtile

// Scratch: zM = z @ M  [B, N, D]  (32 MB)
__device__ float g_zM[(size_t)BATCH * NDIM * DDIM];
// colsum[b, m] = sum_n exp(sigmoid(logits)[b,n,m])
__device__ float g_colsum[BATCH * MEDIM];

// Generic fp32 tiled GEMM: C[M,N] = A[M,K] @ op(B)
//   TRANSB=false: B is [K,N] row-major (ld = Ndim)
//   TRANSB=true:  B is [N,K] row-major (ld = Kdim), i.e. C = A @ B^T
// SIG: apply sigmoid in epilogue.
// Batched via blockIdx.z with per-operand strides (stride 0 to share an operand).
template <bool TRANSB, bool SIG>
__global__ void __launch_bounds__(256) sgemm_kernel(
    const float* __restrict__ A, const float* __restrict__ B, float* __restrict__ C,
    int Mdim, int Ndim, int Kdim,
    long strideA, long strideB, long strideC)
{
    A += (long)blockIdx.z * strideA;
    B += (long)blockIdx.z * strideB;
    C += (long)blockIdx.z * strideC;

    const int blockRow = blockIdx.y * BM;
    const int blockCol = blockIdx.x * BN;

    __shared__ float As[BK][BM];
    __shared__ float Bs[BK][BN];

    const int tid = threadIdx.x;
    const int ty = tid >> 4;   // 0..15
    const int tx = tid & 15;   // 0..15

    float acc[TM][TN];
#pragma unroll
    for (int i = 0; i < TM; i++)
#pragma unroll
        for (int j = 0; j < TN; j++) acc[i][j] = 0.0f;

    for (int k0 = 0; k0 < Kdim; k0 += BK) {
        // ---- Load A tile: [BM x BK] from A[blockRow + r, k0 + c], ld = Kdim
        // 128*16 floats = 512 float4; 2 per thread
#pragma unroll
        for (int it = 0; it < 2; it++) {
            int idx = tid + it * 256;
            int r  = idx >> 2;          // 0..127
            int c4 = (idx & 3) << 2;    // 0,4,8,12
            float4 v = *reinterpret_cast<const float4*>(
                A + (long)(blockRow + r) * Kdim + k0 + c4);
            As[c4 + 0][r] = v.x;
            As[c4 + 1][r] = v.y;
            As[c4 + 2][r] = v.z;
            As[c4 + 3][r] = v.w;
        }
        // ---- Load B tile
        if (TRANSB) {
            // B[blockCol + c, k0 + k], ld = Kdim; store Bs[k][c]
#pragma unroll
            for (int it = 0; it < 2; it++) {
                int idx = tid + it * 256;
                int c  = idx >> 2;          // 0..127
                int k4 = (idx & 3) << 2;    // 0,4,8,12
                float4 v = *reinterpret_cast<const float4*>(
                    B + (long)(blockCol + c) * Kdim + k0 + k4);
                Bs[k4 + 0][c] = v.x;
                Bs[k4 + 1][c] = v.y;
                Bs[k4 + 2][c] = v.z;
                Bs[k4 + 3][c] = v.w;
            }
        } else {
            // B[k0 + r, blockCol + c], ld = Ndim; store Bs[r][c] (vector copy)
#pragma unroll
            for (int it = 0; it < 2; it++) {
                int idx = tid + it * 256;
                int r  = idx >> 5;          // 0..15
                int c4 = (idx & 31) << 2;   // 0..124
                float4 v = *reinterpret_cast<const float4*>(
                    B + (long)(k0 + r) * Ndim + blockCol + c4);
                *reinterpret_cast<float4*>(&Bs[r][c4]) = v;
            }
        }
        __syncthreads();

        // ---- Compute
#pragma unroll
        for (int k = 0; k < BK; k++) {
            float4 a0 = *reinterpret_cast<const float4*>(&As[k][ty * TM]);
            float4 a1 = *reinterpret_cast<const float4*>(&As[k][ty * TM + 4]);
            float4 b0 = *reinterpret_cast<const float4*>(&Bs[k][tx * TN]);
            float4 b1 = *reinterpret_cast<const float4*>(&Bs[k][tx * TN + 4]);
            float ar[TM] = {a0.x, a0.y, a0.z, a0.w, a1.x, a1.y, a1.z, a1.w};
            float br[TN] = {b0.x, b0.y, b0.z, b0.w, b1.x, b1.y, b1.z, b1.w};
#pragma unroll
            for (int i = 0; i < TM; i++)
#pragma unroll
                for (int j = 0; j < TN; j++)
                    acc[i][j] += ar[i] * br[j];
        }
        __syncthreads();
    }

    // ---- Epilogue
#pragma unroll
    for (int i = 0; i < TM; i++) {
        int row = blockRow + ty * TM + i;
#pragma unroll
        for (int jj = 0; jj < TN / 4; jj++) {
            float4 v;
            float* p = &acc[i][jj * 4];
            if (SIG) {
                v.x = 1.0f / (1.0f + expf(-p[0]));
                v.y = 1.0f / (1.0f + expf(-p[1]));
                v.z = 1.0f / (1.0f + expf(-p[2]));
                v.w = 1.0f / (1.0f + expf(-p[3]));
            } else {
                v.x = p[0]; v.y = p[1]; v.z = p[2]; v.w = p[3];
            }
            *reinterpret_cast<float4*>(
                C + (long)row * Ndim + blockCol + tx * TN + jj * 4) = v;
        }
    }
}

// colsum[b, m] = sum_n exp(S[b, n, m])   (S holds sigmoid output, in (0,1))
__global__ void colsum_kernel(const float* __restrict__ S, float* __restrict__ colsum)
{
    int b = blockIdx.y;
    int m = blockIdx.x * blockDim.x + threadIdx.x;
    const float* p = S + (long)b * NDIM * MEDIM + m;
    float s = 0.0f;
#pragma unroll 4
    for (int n = 0; n < NDIM; n++) {
        s += expf(p[(long)n * MEDIM]);
    }
    colsum[b * MEDIM + m] = s;
}

// In-place: S[b,n,m] = exp(S[b,n,m]) / colsum[b,m]
__global__ void softmax_norm_kernel(float* __restrict__ S, const float* __restrict__ colsum)
{
    int b = blockIdx.y;
    long i = (long)blockIdx.x * blockDim.x + threadIdx.x;  // within batch, 0..N*ME-1
    int m = (int)(i & (MEDIM - 1));
    float* p = S + (long)b * NDIM * MEDIM + i;
    *p = expf(*p) / colsum[b * MEDIM + m];
}

extern "C" void kernel_launch(void* const* d_in, const int* in_sizes, int n_in,
                              void* d_out, int out_size)
{
    const float* z = (const float*)d_in[0];   // [B, N, D]
    const float* e = (const float*)d_in[1];   // [B, ME, D]
    const float* M = (const float*)d_in[2];   // [D, D]

    float* e_out = (float*)d_out;                                   // [B, N, D]
    float* A_out = (float*)d_out + (size_t)BATCH * NDIM * DDIM;     // [B, N, ME]

    float* zM = nullptr;
    float* colsum = nullptr;
    cudaGetSymbolAddress((void**)&zM, g_zM);
    cudaGetSymbolAddress((void**)&colsum, g_colsum);

    const long sNB = (long)NDIM * DDIM;    // z / zM / e_out per-batch stride
    const long sEB = (long)MEDIM * DDIM;   // e per-batch stride
    const long sAB = (long)NDIM * MEDIM;   // logits/A per-batch stride

    dim3 block(256);

    // 1) zM[b] = z[b] @ M          (NN, shared B, stride 0)
    {
        dim3 grid(DDIM / BN, NDIM / BM, BATCH);
        sgemm_kernel<false, false><<<grid, block>>>(
            z, M, zM, NDIM, DDIM, DDIM, sNB, 0, sNB);
    }

    // 2) s[b] = sigmoid(zM[b] @ e[b]^T)   -> written into A_out region
    {
        dim3 grid(MEDIM / BN, NDIM / BM, BATCH);
        sgemm_kernel<true, true><<<grid, block>>>(
            zM, e, A_out, NDIM, MEDIM, DDIM, sNB, sEB, sAB);
    }

    // 3) column sums of exp(s) over the N axis
    {
        dim3 grid(MEDIM / 256, BATCH);
        colsum_kernel<<<grid, block>>>(A_out, colsum);
    }

    // 4) A = exp(s) / colsum   (in place)
    {
        dim3 grid((NDIM * MEDIM) / 256, BATCH);
        softmax_norm_kernel<<<grid, block>>>(A_out, colsum);
    }

    // 5) e_out[b] = A[b] @ e[b]   (NN)
    {
        dim3 grid(DDIM / BN, NDIM / BM, BATCH);
        sgemm_kernel<false, false><<<grid, block>>>(
            A_out, e, e_out, NDIM, DDIM, MEDIM, sAB, sEB, sNB);
    }
}

// round 6
// speedup vs baseline: 1.4704x; 1.4704x over previous
#include <cuda_runtime.h>
#include <cuda_bf16.h>
#include <cstdint>
#include <math.h>

// Problem constants
#define BATCH 8
#define NDIM  1024
#define MEDIM 1024
#define DDIM  1024

typedef __nv_bfloat16 bf16;

// ============================================================================
// Scratch (device globals; no allocation allowed)
// ============================================================================
#define EL8M ((size_t)BATCH * 1024 * 1024)
__device__ bf16 g_z1[EL8M], g_z2[EL8M], g_z3[EL8M];                 // z limbs [B,N,D]
__device__ bf16 g_m1[1024*1024], g_m2[1024*1024], g_m3[1024*1024];  // M^T limbs [D,D]
__device__ bf16 g_p1[EL8M], g_p2[EL8M], g_p3[EL8M];                 // zM limbs [B,N,D]
__device__ bf16 g_e1[EL8M], g_e2[EL8M], g_e3[EL8M];                 // e limbs [B,ME,D]
__device__ bf16 g_t1[EL8M], g_t2[EL8M];                             // e^T limbs [B,D,ME]
__device__ bf16 g_a1[EL8M], g_a2[EL8M];                             // A limbs [B,N,ME]
__device__ float g_colsum[BATCH * MEDIM];

// ============================================================================
// PTX helpers (compute_103-safe: mma.sync / ldmatrix / cp.async only)
// ============================================================================
__device__ __forceinline__ uint32_t smem_u32(const void* p) {
    uint32_t a;
    asm("{ .reg .u64 t; cvta.to.shared.u64 t, %1; cvt.u32.u64 %0, t; }" : "=r"(a) : "l"(p));
    return a;
}

#define CP_ASYNC16(dst, src) \
    asm volatile("cp.async.cg.shared.global [%0], [%1], 16;" :: "r"(dst), "l"(src))
#define CP_COMMIT() asm volatile("cp.async.commit_group;" ::: "memory")
#define CP_WAIT2()  asm volatile("cp.async.wait_group 2;" ::: "memory")

#define LDMATRIX_X4(r, addr) \
    asm volatile("ldmatrix.sync.aligned.m8n8.x4.shared.b16 {%0,%1,%2,%3}, [%4];" \
        : "=r"((r)[0]), "=r"((r)[1]), "=r"((r)[2]), "=r"((r)[3]) : "r"(addr))

#define MMA16816(d, a, b0, b1) \
    asm volatile("mma.sync.aligned.m16n8k16.row.col.f32.bf16.bf16.f32 " \
        "{%0,%1,%2,%3}, {%4,%5,%6,%7}, {%8,%9}, {%0,%1,%2,%3};" \
        : "+f"((d)[0]), "+f"((d)[1]), "+f"((d)[2]), "+f"((d)[3]) \
        : "r"((a)[0]), "r"((a)[1]), "r"((a)[2]), "r"((a)[3]), "r"(b0), "r"(b1))

#define SWZ(x) ((x) ^ (((x) >> 3) & 0x70))

// ============================================================================
// Split helpers
// ============================================================================
__device__ __forceinline__ void split3f(float v, bf16& h, bf16& m, bf16& l) {
    h = __float2bfloat16(v);
    float r = v - __bfloat162float(h);
    m = __float2bfloat16(r);
    l = __float2bfloat16(r - __bfloat162float(m));
}
__device__ __forceinline__ void split2f(float v, bf16& h, bf16& l) {
    h = __float2bfloat16(v);
    l = __float2bfloat16(v - __bfloat162float(h));
}

__global__ void split3_kernel(const float* __restrict__ x, bf16* __restrict__ h,
                              bf16* __restrict__ m, bf16* __restrict__ l) {
    size_t i = (size_t)blockIdx.x * blockDim.x + threadIdx.x;
    split3f(x[i], h[i], m[i], l[i]);
}

// transpose + 3-split (single 1024x1024 matrix): out[r][c] = in[c][r]
__global__ void tsplit3_kernel(const float* __restrict__ x, bf16* __restrict__ h,
                               bf16* __restrict__ m, bf16* __restrict__ l) {
    __shared__ float tile[32][33];
    int x0 = blockIdx.x * 32, y0 = blockIdx.y * 32;
    for (int i = threadIdx.y; i < 32; i += 8)
        tile[i][threadIdx.x] = x[(size_t)(y0 + i) * 1024 + x0 + threadIdx.x];
    __syncthreads();
    for (int i = threadIdx.y; i < 32; i += 8) {
        float v = tile[threadIdx.x][i];
        size_t o = (size_t)(x0 + i) * 1024 + y0 + threadIdx.x;
        split3f(v, h[o], m[o], l[o]);
    }
}

// batched transpose + 2-split: out[b][r][c] = in[b][c][r]
__global__ void tsplit2_kernel(const float* __restrict__ x, bf16* __restrict__ h,
                               bf16* __restrict__ l) {
    __shared__ float tile[32][33];
    size_t boff = (size_t)blockIdx.z * 1024 * 1024;
    int x0 = blockIdx.x * 32, y0 = blockIdx.y * 32;
    for (int i = threadIdx.y; i < 32; i += 8)
        tile[i][threadIdx.x] = x[boff + (size_t)(y0 + i) * 1024 + x0 + threadIdx.x];
    __syncthreads();
    for (int i = threadIdx.y; i < 32; i += 8) {
        float v = tile[threadIdx.x][i];
        size_t o = boff + (size_t)(x0 + i) * 1024 + y0 + threadIdx.x;
        split2f(v, h[o], l[o]);
    }
}

// ============================================================================
// bf16 tensor-core GEMM (mma.sync m16n8k16), Ozaki multi-segment K.
// C[128x128 tile] = sum_seg A_seg[128,1024] @ B_seg[128,1024]^T
// Both operands K-major bf16. EPI: 0=f32 store, 1=sigmoid f32, 2=3-limb bf16.
// ============================================================================
struct GemmParams {
    const bf16* a[6];
    const bf16* b[6];
    long strideA, strideB, strideC;
    float* C;
    bf16 *oh, *om, *ol;
};

#define STAGE_BYTES 32768u   // A 16KB + B 16KB
#define SMEM_BYTES  98304    // 3 stages

template <int NSEG, int EPI>
__global__ void __launch_bounds__(256, 2) mm_kernel(GemmParams p) {
    extern __shared__ char smem[];
    const uint32_t sb = smem_u32(smem);
    const int tid = threadIdx.x;
    const int lid = tid & 31;
    const int wid = tid >> 5;
    const int wm = wid & 3;    // 0..3 -> 32-row slice
    const int wn = wid >> 2;   // 0..1 -> 64-col slice

    const int b = blockIdx.z;
    const long row0 = (long)blockIdx.y * 128;
    const long col0 = (long)blockIdx.x * 128;

    const int NCH = NSEG * 16;   // K chunks of 64

    float acc[2][8][4];
#pragma unroll
    for (int i = 0; i < 2; i++)
#pragma unroll
        for (int j = 0; j < 8; j++)
#pragma unroll
            for (int k = 0; k < 4; k++) acc[i][j][k] = 0.0f;

    // Per chunk each operand tile is 128 rows x 128 bytes = 16KB = 1024 x 16B.
    // 256 threads x 4 iters x (1 A + 1 B) x 16B = full 32KB stage.
    auto load_chunk = [&](int c, int stage) {
        const int seg = c >> 4;
        const long kk = (long)(c & 15) << 6;
        const bf16* Ag = p.a[seg] + (long)b * p.strideA + kk;
        const bf16* Bg = p.b[seg] + (long)b * p.strideB + kk;
        const uint32_t sa = sb + (uint32_t)stage * STAGE_BYTES;
        const uint32_t sbb = sa + 16384u;
#pragma unroll
        for (int t = 0; t < 4; t++) {
            int idx = tid + (t << 8);          // 0..1023
            int r = idx >> 3;                  // 0..127
            int c16 = idx & 7;                 // 0..7 (16B units across 128B row)
            uint32_t bo = (uint32_t)(r << 7) + (uint32_t)(c16 << 4);
            CP_ASYNC16(sa  + SWZ(bo), Ag + (row0 + r) * 1024 + (c16 << 3));
            CP_ASYNC16(sbb + SWZ(bo), Bg + (col0 + r) * 1024 + (c16 << 3));
        }
    };

    load_chunk(0, 0); CP_COMMIT();
    load_chunk(1, 1); CP_COMMIT();

    for (int c = 0; c < NCH; c++) {
        if (c + 2 < NCH) load_chunk(c + 2, (c + 2) % 3);
        CP_COMMIT();
        CP_WAIT2();
        __syncthreads();

        const uint32_t sa  = sb + (uint32_t)(c % 3) * STAGE_BYTES;
        const uint32_t sbb = sa + 16384u;

#pragma unroll
        for (int j = 0; j < 4; j++) {       // k16 step within 64-chunk
            uint32_t af[2][4];
#pragma unroll
            for (int mi = 0; mi < 2; mi++) {
                int row = wm * 32 + mi * 16 + (lid & 15);
                uint32_t bo = (uint32_t)(row << 7) + (uint32_t)(j << 5)
                            + (uint32_t)((lid >> 4) << 4);
                LDMATRIX_X4(af[mi], sa + SWZ(bo));
            }
#pragma unroll
            for (int ni = 0; ni < 4; ni++) {  // 16-col groups
                uint32_t bfr[4];
                int nr = wn * 64 + ni * 16 + (lid & 7) + (((lid >> 4) & 1) << 3);
                uint32_t bo = (uint32_t)(nr << 7) + (uint32_t)(j << 5)
                            + (uint32_t)(((lid >> 3) & 1) << 4);
                LDMATRIX_X4(bfr, sbb + SWZ(bo));
#pragma unroll
                for (int mi = 0; mi < 2; mi++) {
                    MMA16816(acc[mi][ni * 2 + 0], af[mi], bfr[0], bfr[1]);
                    MMA16816(acc[mi][ni * 2 + 1], af[mi], bfr[2], bfr[3]);
                }
            }
        }
        __syncthreads();
    }

    // ---- Epilogue (direct from registers) ----
    const int r_in = lid >> 2;
    const int c_in = (lid & 3) << 1;
#pragma unroll
    for (int mi = 0; mi < 2; mi++) {
        const long row = row0 + wm * 32 + mi * 16 + r_in;
#pragma unroll
        for (int nj = 0; nj < 8; nj++) {
            const long colg = col0 + wn * 64 + nj * 8 + c_in;
            float v0 = acc[mi][nj][0], v1 = acc[mi][nj][1];
            float v2 = acc[mi][nj][2], v3 = acc[mi][nj][3];
            if (EPI == 0 || EPI == 1) {
                if (EPI == 1) {
                    v0 = 1.0f / (1.0f + expf(-v0));
                    v1 = 1.0f / (1.0f + expf(-v1));
                    v2 = 1.0f / (1.0f + expf(-v2));
                    v3 = 1.0f / (1.0f + expf(-v3));
                }
                float* Cp = p.C + (long)b * p.strideC;
                *reinterpret_cast<float2*>(Cp + row * 1024 + colg)       = make_float2(v0, v1);
                *reinterpret_cast<float2*>(Cp + (row + 8) * 1024 + colg) = make_float2(v2, v3);
            } else {
                const long base0 = (long)b * p.strideC + row * 1024 + colg;
                const long base1 = base0 + 8 * 1024;
                bf16 h0, m0, l0, h1, m1, l1;
                split3f(v0, h0, m0, l0); split3f(v1, h1, m1, l1);
                *reinterpret_cast<__nv_bfloat162*>(p.oh + base0) = __nv_bfloat162(h0, h1);
                *reinterpret_cast<__nv_bfloat162*>(p.om + base0) = __nv_bfloat162(m0, m1);
                *reinterpret_cast<__nv_bfloat162*>(p.ol + base0) = __nv_bfloat162(l0, l1);
                split3f(v2, h0, m0, l0); split3f(v3, h1, m1, l1);
                *reinterpret_cast<__nv_bfloat162*>(p.oh + base1) = __nv_bfloat162(h0, h1);
                *reinterpret_cast<__nv_bfloat162*>(p.om + base1) = __nv_bfloat162(m0, m1);
                *reinterpret_cast<__nv_bfloat162*>(p.ol + base1) = __nv_bfloat162(l0, l1);
            }
        }
    }
}

// ============================================================================
// Softmax pieces
// ============================================================================
__global__ void colsum_kernel(const float* __restrict__ S, float* __restrict__ cs) {
    int b = blockIdx.y;
    int m = blockIdx.x * blockDim.x + threadIdx.x;
    const float* p = S + (size_t)b * NDIM * MEDIM + m;
    float s = 0.0f;
#pragma unroll 4
    for (int n = 0; n < NDIM; n++) s += expf(p[(size_t)n * MEDIM]);
    cs[b * MEDIM + m] = s;
}

// A = exp(S)/colsum (in place), plus 2-limb bf16 split of A
__global__ void softmax_split_kernel(float* __restrict__ S, const float* __restrict__ cs,
                                     bf16* __restrict__ ah, bf16* __restrict__ al) {
    size_t g = (size_t)blockIdx.x * blockDim.x + threadIdx.x;
    int b = (int)(g >> 20);
    int m = (int)(g & (MEDIM - 1));
    float v = expf(S[g]) / cs[b * MEDIM + m];
    S[g] = v;
    split2f(v, ah[g], al[g]);
}

// ============================================================================
// Host launch
// ============================================================================
extern "C" void kernel_launch(void* const* d_in, const int* in_sizes, int n_in,
                              void* d_out, int out_size) {
    const float* z = (const float*)d_in[0];
    const float* e = (const float*)d_in[1];
    const float* M = (const float*)d_in[2];

    float* e_out = (float*)d_out;
    float* A_out = (float*)d_out + (size_t)BATCH * NDIM * DDIM;

    bf16 *z1, *z2, *z3, *m1, *m2, *m3, *p1, *p2, *p3, *e1, *e2, *e3, *t1, *t2, *a1, *a2;
    float* cs;
    cudaGetSymbolAddress((void**)&z1, g_z1); cudaGetSymbolAddress((void**)&z2, g_z2);
    cudaGetSymbolAddress((void**)&z3, g_z3);
    cudaGetSymbolAddress((void**)&m1, g_m1); cudaGetSymbolAddress((void**)&m2, g_m2);
    cudaGetSymbolAddress((void**)&m3, g_m3);
    cudaGetSymbolAddress((void**)&p1, g_p1); cudaGetSymbolAddress((void**)&p2, g_p2);
    cudaGetSymbolAddress((void**)&p3, g_p3);
    cudaGetSymbolAddress((void**)&e1, g_e1); cudaGetSymbolAddress((void**)&e2, g_e2);
    cudaGetSymbolAddress((void**)&e3, g_e3);
    cudaGetSymbolAddress((void**)&t1, g_t1); cudaGetSymbolAddress((void**)&t2, g_t2);
    cudaGetSymbolAddress((void**)&a1, g_a1); cudaGetSymbolAddress((void**)&a2, g_a2);
    cudaGetSymbolAddress((void**)&cs, g_colsum);

    cudaFuncSetAttribute(mm_kernel<6, 2>, cudaFuncAttributeMaxDynamicSharedMemorySize, SMEM_BYTES);
    cudaFuncSetAttribute(mm_kernel<6, 1>, cudaFuncAttributeMaxDynamicSharedMemorySize, SMEM_BYTES);
    cudaFuncSetAttribute(mm_kernel<3, 0>, cudaFuncAttributeMaxDynamicSharedMemorySize, SMEM_BYTES);

    const long S8 = (long)1024 * 1024;

    // ---- Prep: limb splits ----
    split3_kernel<<<(BATCH * S8) / 256, 256>>>(z, z1, z2, z3);
    split3_kernel<<<(BATCH * S8) / 256, 256>>>(e, e1, e2, e3);
    tsplit3_kernel<<<dim3(32, 32, 1), dim3(32, 8)>>>(M, m1, m2, m3);
    tsplit2_kernel<<<dim3(32, 32, BATCH), dim3(32, 8)>>>(e, t1, t2);

    dim3 gg(8, 8, BATCH);   // cols/128, rows/128, batch
    dim3 gb(256);

    // ---- GEMM1: zM = z @ M  (limb pairs hh,hm,mh,hl,mm,lh) -> zM limbs ----
    {
        GemmParams p{};
        p.a[0] = z1; p.a[1] = z1; p.a[2] = z2; p.a[3] = z1; p.a[4] = z2; p.a[5] = z3;
        p.b[0] = m1; p.b[1] = m2; p.b[2] = m1; p.b[3] = m3; p.b[4] = m2; p.b[5] = m1;
        p.strideA = S8; p.strideB = 0; p.strideC = S8;
        p.oh = p1; p.om = p2; p.ol = p3; p.C = nullptr;
        mm_kernel<6, 2><<<gg, gb, SMEM_BYTES>>>(p);
    }
    // ---- GEMM2: S = sigmoid(zM @ e^T) ----
    {
        GemmParams p{};
        p.a[0] = p1; p.a[1] = p1; p.a[2] = p2; p.a[3] = p1; p.a[4] = p2; p.a[5] = p3;
        p.b[0] = e1; p.b[1] = e2; p.b[2] = e1; p.b[3] = e3; p.b[4] = e2; p.b[5] = e1;
        p.strideA = S8; p.strideB = S8; p.strideC = S8;
        p.C = A_out;
        mm_kernel<6, 1><<<gg, gb, SMEM_BYTES>>>(p);
    }
    // ---- Softmax over N (column axis) ----
    colsum_kernel<<<dim3(MEDIM / 256, BATCH), gb>>>(A_out, cs);
    softmax_split_kernel<<<(BATCH * S8) / 256, 256>>>(A_out, cs, a1, a2);

    // ---- GEMM3: e_out = A @ e  (limb pairs hh,hl,lh) ----
    {
        GemmParams p{};
        p.a[0] = a1; p.a[1] = a1; p.a[2] = a2;
        p.b[0] = t1; p.b[1] = t2; p.b[2] = t1;
        p.strideA = S8; p.strideB = S8; p.strideC = S8;
        p.C = e_out;
        mm_kernel<3, 0><<<gg, gb, SMEM_BYTES>>>(p);
    }
}